// round 13
// baseline (speedup 1.0000x reference)
#include <cuda_runtime.h>
#include <float.h>

// Scratch accumulators — zero-initialized at module load; the kernel resets
// them at the end of every invocation so each graph replay starts clean.
__device__ float        g_sum[4096 * 128];     // segment sums
__device__ unsigned int g_maxk[4096 * 128];    // order-preserving max keys; 0 == -inf
__device__ int          g_counts[4096];        // segment element counts
__device__ unsigned int g_arrive;              // grid barrier: arrivals
__device__ unsigned int g_depart;              // grid barrier: departures

// Order-preserving float<->uint key. Monotone: f1 < f2 <=> key(f1) < key(f2).
// key(x) >= 1 for all finite x, so a zero key acts as -infinity.
__device__ __forceinline__ unsigned int fkey(float f) {
    unsigned int b = __float_as_uint(f);
    return (b & 0x80000000u) ? ~b : (b | 0x80000000u);
}
__device__ __forceinline__ float funkey(unsigned int k) {
    return __uint_as_float((k & 0x80000000u) ? (k & 0x7FFFFFFFu) : ~k);
}

struct Acc {
    float4 s, m;
    int cnt, cur;
};

__device__ __forceinline__ void flush_acc(const Acc& a, int lane, int B) {
    int cc = min(max(a.cur, 0), B - 1);
    float* sb = g_sum + cc * 128 + lane * 4;
    atomicAdd(sb + 0, a.s.x);
    atomicAdd(sb + 1, a.s.y);
    atomicAdd(sb + 2, a.s.z);
    atomicAdd(sb + 3, a.s.w);
    unsigned int* mb = g_maxk + cc * 128 + lane * 4;
    atomicMax(mb + 0, fkey(a.m.x));
    atomicMax(mb + 1, fkey(a.m.y));
    atomicMax(mb + 2, fkey(a.m.z));
    atomicMax(mb + 3, fkey(a.m.w));
    if (lane == 0) atomicAdd(&g_counts[cc], a.cnt);
}

__device__ __forceinline__ void step_acc(Acc& a, int b, float4 v,
                                         int lane, int B) {
    if (b != a.cur) {
        flush_acc(a, lane, B);
        a.s = make_float4(0.f, 0.f, 0.f, 0.f);
        a.m = make_float4(-FLT_MAX, -FLT_MAX, -FLT_MAX, -FLT_MAX);
        a.cnt = 0;
        a.cur = b;
    }
    a.s.x += v.x; a.s.y += v.y; a.s.z += v.z; a.s.w += v.w;
    a.m.x = fmaxf(a.m.x, v.x);
    a.m.y = fmaxf(a.m.y, v.y);
    a.m.z = fmaxf(a.m.z, v.z);
    a.m.w = fmaxf(a.m.w, v.w);
    a.cnt++;
}

// Fused aggregate + finalize. Phase 1: one warp per contiguous 4-aligned row
// range, register accumulation, atomic flush to scratch on segment change.
// Grid-wide software barrier — safe because the host launches exactly
// 6 CTAs/SM and __launch_bounds__(256, 6) guarantees 6 CTAs/SM residency,
// so every block is co-resident regardless of the actual SM count.
// Phase 2: one thread per (segment, float4-group) reads scratch, writes
// [sum|mean|max], resets scratch. Last departing block resets the barrier.
__global__ void __launch_bounds__(256, 6) fused_kernel(
    const float4* __restrict__ x,       // [N, 32] float4 view of [N, 128]
    const int* __restrict__ batch,      // [N] sorted segment ids (int32)
    float* __restrict__ out,            // [B, 384]
    int N, int B)
{
    const int gtid   = blockIdx.x * blockDim.x + threadIdx.x;
    const int warp   = gtid >> 5;
    const int lane   = gtid & 31;
    const int nwarps = (gridDim.x * blockDim.x) >> 5;

    // ---------------- Phase 1: aggregation ----------------
    // 4-row-aligned contiguous ranges (keeps int4 batch loads aligned).
    long long start = (((long long)N * warp / nwarps) + 3) & ~3LL;
    long long end   = (((long long)N * (warp + 1) / nwarps) + 3) & ~3LL;
    if (end > N) end = N;

    if (start < end) {
        Acc a;
        a.s = make_float4(0.f, 0.f, 0.f, 0.f);
        a.m = make_float4(-FLT_MAX, -FLT_MAX, -FLT_MAX, -FLT_MAX);
        a.cnt = 0;
        a.cur = __ldcs(&batch[start]);

        long long r = start;
        for (; r + 4 <= end; r += 4) {
            int4 b4 = __ldcs((const int4*)&batch[r]);
            float4 v0 = __ldcs(&x[(r + 0) * 32 + lane]);
            float4 v1 = __ldcs(&x[(r + 1) * 32 + lane]);
            float4 v2 = __ldcs(&x[(r + 2) * 32 + lane]);
            float4 v3 = __ldcs(&x[(r + 3) * 32 + lane]);
            step_acc(a, b4.x, v0, lane, B);
            step_acc(a, b4.y, v1, lane, B);
            step_acc(a, b4.z, v2, lane, B);
            step_acc(a, b4.w, v3, lane, B);
        }
        for (; r < end; ++r) {
            int b = __ldcs(&batch[r]);
            float4 v = __ldcs(&x[r * 32 + lane]);
            step_acc(a, b, v, lane, B);
        }
        flush_acc(a, lane, B);
    }

    // ---------------- Grid-wide barrier ----------------
    __threadfence();          // make this block's atomics globally visible
    __syncthreads();          // all warps in block done flushing
    if (threadIdx.x == 0) {
        atomicAdd(&g_arrive, 1u);
        while (atomicAdd(&g_arrive, 0u) < gridDim.x) {
            __nanosleep(128);
        }
    }
    __syncthreads();
    __threadfence();          // acquire: see all blocks' flushes

    // ---------------- Phase 2: finalize ----------------
    // One item per thread: i in [0, B*32). Segment b = i>>5 spans exactly one
    // warp, so the g_counts read/reset pair only needs __syncwarp ordering.
    if (gtid < B * 32) {
        int i  = gtid;
        int b  = i >> 5;
        int h4 = i & 31;

        float4 s = ((const float4*)g_sum)[i];
        uint4  k = ((const uint4*)g_maxk)[i];
        int    c = g_counts[b];
        __syncwarp();         // all lanes read g_counts[b] before lane resets it

        float inv = 1.0f / fmaxf((float)c, 1.0f);
        float4 mean = make_float4(s.x * inv, s.y * inv, s.z * inv, s.w * inv);
        float4 mx;
        if (c > 0) {
            mx = make_float4(funkey(k.x), funkey(k.y), funkey(k.z), funkey(k.w));
        } else {
            mx = make_float4(0.f, 0.f, 0.f, 0.f);
        }

        float4* row = (float4*)(out + (long long)b * 384);
        __stcs(row + h4,      s);
        __stcs(row + 32 + h4, mean);
        __stcs(row + 64 + h4, mx);

        // Reset scratch for next replay.
        ((float4*)g_sum)[i] = make_float4(0.f, 0.f, 0.f, 0.f);
        ((uint4*)g_maxk)[i] = make_uint4(0u, 0u, 0u, 0u);
        if (h4 == 0) g_counts[b] = 0;
    }

    // ---------------- Departure: last block resets barrier ----------------
    __threadfence();
    __syncthreads();
    if (threadIdx.x == 0) {
        unsigned int t = atomicAdd(&g_depart, 1u);
        if (t == gridDim.x - 1) {
            // All other blocks have finished both phases and will never touch
            // the counters again this launch; safe to reset with plain stores.
            g_arrive = 0u;
            g_depart = 0u;
            __threadfence();
        }
    }
}

extern "C" void kernel_launch(void* const* d_in, const int* in_sizes, int n_in,
                              void* d_out, int out_size) {
    const float4* x  = (const float4*)d_in[0];
    const int* batch = (const int*)d_in[1];   // int32 on device (verified)
    float* out       = (float*)d_out;

    int N = in_sizes[1];           // number of rows
    int B = out_size / 384;        // segments (out is [B, 3*128])

    // Grid must be exactly 6 CTAs per SM so the in-kernel grid barrier is
    // deadlock-free: __launch_bounds__(256, 6) guarantees 6-CTA residency.
    // Query the real SM count (148 on B300 die; do NOT hard-code).
    static int sm_count = 0;
    if (sm_count == 0) {
        int dev = 0;
        cudaGetDevice(&dev);
        cudaDeviceGetAttribute(&sm_count, cudaDevAttrMultiProcessorCount, dev);
        if (sm_count <= 0) sm_count = 148;   // conservative fallback
    }
    int blocks = 6 * sm_count;

    fused_kernel<<<blocks, 256>>>(x, batch, out, N, B);
}